// round 3
// baseline (speedup 1.0000x reference)
#include <cuda_runtime.h>
#include <math.h>

// Shapes (fixed):
//   x: (1024,1,63,250) fp32 -> nodes (63, 256000), k = a*250 + d
//   W: (256000, 256) fp32; att_src/att_dst/bias: (256,); out: (63,1)
#define NA    1024
#define NC    63
#define ND    250
#define NOUT  256
#define BPA   32            // blocks per batch index a (32*8 = 256 >= 250 rows)

// ---- scratch ----
__device__ float4 g_v4[NA * ND];            // (w.att_src, w.att_dst, rowsum/256, 0)
__device__ float  g_partial[3 * NC * NA];   // [t*63+c][a]
__device__ float  g_out3[3 * NC];
__device__ float  g_bm;
__device__ int    g_actr[NA];               // per-a completion counters (zero-init)
__device__ int    g_ctr = 0;

// ============================================================================
// Kernel 1: W projection (R1 structure: one warp = one row, 8 rows/block)
// + per-a elected block runs the x contraction for that a (R1 nodes body).
// ============================================================================
__global__ void __launch_bounds__(256) main_kernel(
    const float* __restrict__ x,
    const float* __restrict__ W,
    const float* __restrict__ att_src,
    const float* __restrict__ att_dst)
{
    const int a    = blockIdx.x >> 5;          // batch index
    const int r8   = blockIdx.x & (BPA - 1);   // 8-row group within a
    const int warp = threadIdx.x >> 5;
    const int lane = threadIdx.x & 31;
    const int d    = r8 * 8 + warp;            // row within a (0..255; valid < 250)

    // ---- Phase A: project row k = a*250 + d (exact R1 proj_w body) ----
    if (d < ND) {
        const int k = a * ND + d;
        const float4* __restrict__ Wr =
            reinterpret_cast<const float4*>(W) + (size_t)k * (NOUT / 4);
        const float4* __restrict__ s4 = reinterpret_cast<const float4*>(att_src);
        const float4* __restrict__ d4 = reinterpret_cast<const float4*>(att_dst);

        float4 w0 = Wr[lane];
        float4 w1 = Wr[lane + 32];
        float4 a0 = s4[lane];
        float4 a1 = s4[lane + 32];
        float4 b0 = d4[lane];
        float4 b1 = d4[lane + 32];

        float ss = w0.x * a0.x + w0.y * a0.y + w0.z * a0.z + w0.w * a0.w
                 + w1.x * a1.x + w1.y * a1.y + w1.z * a1.z + w1.w * a1.w;
        float sd = w0.x * b0.x + w0.y * b0.y + w0.z * b0.z + w0.w * b0.w
                 + w1.x * b1.x + w1.y * b1.y + w1.z * b1.z + w1.w * b1.w;
        float sm = w0.x + w0.y + w0.z + w0.w + w1.x + w1.y + w1.z + w1.w;

        #pragma unroll
        for (int off = 16; off > 0; off >>= 1) {
            ss += __shfl_xor_sync(0xffffffffu, ss, off);
            sd += __shfl_xor_sync(0xffffffffu, sd, off);
            sm += __shfl_xor_sync(0xffffffffu, sm, off);
        }
        if (lane == 0)
            g_v4[k] = make_float4(ss, sd, sm * (1.0f / 256.0f), 0.0f);
    }

    // ---- Election: last of the 32 blocks for this a does phase B ----
    __threadfence();
    __syncthreads();
    __shared__ int s_elect;
    if (threadIdx.x == 0)
        s_elect = (atomicAdd(&g_actr[a], 1) == BPA - 1);
    __syncthreads();
    if (!s_elect) return;
    if (threadIdx.x == 0) g_actr[a] = 0;       // reset for next graph replay

    // ---- Phase B: x contraction for this a (exact R1 nodes body) ----
    __shared__ float4 sv[ND];
    for (int i = threadIdx.x; i < ND; i += 256)
        sv[i] = __ldcg(&g_v4[a * ND + i]);
    __syncthreads();

    const float* __restrict__ xa = x + (size_t)a * (NC * ND);
    for (int c = warp; c < NC; c += 8) {
        const float* __restrict__ xr = xa + c * ND;
        float p0 = 0.f, p1 = 0.f, p2 = 0.f;
        for (int i = lane; i < ND; i += 32) {
            const float  xv = xr[i];
            const float4 v  = sv[i];
            p0 = fmaf(xv, v.x, p0);
            p1 = fmaf(xv, v.y, p1);
            p2 = fmaf(xv, v.z, p2);
        }
        #pragma unroll
        for (int off = 16; off > 0; off >>= 1) {
            p0 += __shfl_xor_sync(0xffffffffu, p0, off);
            p1 += __shfl_xor_sync(0xffffffffu, p1, off);
            p2 += __shfl_xor_sync(0xffffffffu, p2, off);
        }
        if (lane == 0) {
            g_partial[(0 * NC + c) * NA + a] = p0;
            g_partial[(1 * NC + c) * NA + a] = p1;
            g_partial[(2 * NC + c) * NA + a] = p2;
        }
    }
}

// ============================================================================
// Kernel 2: reduce 1024 partials per slot (189 blocks, float4 loads) + bias
// mean (block 189); last-arriving block runs the 63x63 softmax.
// ============================================================================
__global__ void __launch_bounds__(256) finish_kernel(
    const float* __restrict__ bias, float* __restrict__ out)
{
    const int b   = blockIdx.x;     // 0..188 partial slots, 189 = bias
    const int tid = threadIdx.x;
    __shared__ float sh[256];

    if (b < 3 * NC) {
        const float4* __restrict__ p4 =
            reinterpret_cast<const float4*>(g_partial + b * NA);
        const float4 v = p4[tid];                 // one LDG.128 per thread
        sh[tid] = (v.x + v.y) + (v.z + v.w);
    } else {
        sh[tid] = bias[tid];
    }
    __syncthreads();
    #pragma unroll
    for (int st = 128; st > 0; st >>= 1) {
        if (tid < st) sh[tid] += sh[tid + st];
        __syncthreads();
    }
    if (tid == 0) {
        if (b < 3 * NC) g_out3[b] = sh[0];
        else            g_bm = sh[0] * (1.0f / 256.0f);
    }

    // ---- last-block softmax ----
    __threadfence();
    __shared__ int is_last;
    if (tid == 0) is_last = (atomicAdd(&g_ctr, 1) == 3 * NC);  // 190 blocks
    __syncthreads();
    if (!is_last) return;

    __shared__ float as_[NC], ad_[NC], hb_[NC], bm_s;
    if (tid < NC)            as_[tid]         = __ldcg(&g_out3[0 * NC + tid]);
    else if (tid < 2 * NC)   ad_[tid - NC]    = __ldcg(&g_out3[1 * NC + (tid - NC)]);
    else if (tid < 3 * NC)   hb_[tid - 2*NC]  = __ldcg(&g_out3[2 * NC + (tid - 2*NC)]);
    if (tid == 0) bm_s = __ldcg(&g_bm);
    __syncthreads();

    if (tid < NC) {
        const float ai = ad_[tid];
        float m = -1e30f;
        #pragma unroll 7
        for (int j = 0; j < NC; j++) {
            float e = ai + as_[j];
            e = (e > 0.f) ? e : 0.2f * e;
            m = fmaxf(m, e);
        }
        float Z = 0.f, S = 0.f;
        #pragma unroll 7
        for (int j = 0; j < NC; j++) {
            float e = ai + as_[j];
            e = (e > 0.f) ? e : 0.2f * e;
            const float w = __expf(e - m);
            Z += w;
            S = fmaf(w, hb_[j], S);
        }
        out[tid] = S / Z + bm_s;
    }
    if (tid == 0) g_ctr = 0;   // reset for next graph replay
}

// ============================================================================
extern "C" void kernel_launch(void* const* d_in, const int* in_sizes, int n_in,
                              void* d_out, int out_size)
{
    const float* x       = (const float*)d_in[0];
    const float* W       = (const float*)d_in[1];
    const float* att_src = (const float*)d_in[2];
    const float* att_dst = (const float*)d_in[3];
    const float* bias    = (const float*)d_in[4];
    float* out = (float*)d_out;

    main_kernel<<<NA * BPA, 256>>>(x, W, att_src, att_dst);
    finish_kernel<<<3 * NC + 1, 256>>>(bias, out);
}